// round 2
// baseline (speedup 1.0000x reference)
#include <cuda_runtime.h>

// TripletLoss fused single-kernel: N=384, D=128, 16 classes, margin=0.3
//
// One launch. Each of 96 blocks stages the full embedding matrix E (384x128 f32)
// into padded shared memory, computes dist rows for its 4 anchors via packed
// f32x2 FMAs, runs the triplet accumulation with deterministic ballot-compacted
// positives, and the last-finishing block (ticket counter) reduces the 96 block
// partials and writes out[0]=loss_sum, out[1]=count. No memset needed.

#define MARGIN_F 0.3f
constexpr int NPTS = 384;
constexpr int DIM  = 128;
constexpr int NB   = 96;    // blocks
constexpr int APB  = 4;     // anchors per block
constexpr int ROWF = 132;   // padded row stride (floats): 16B-aligned, conflict-free LDS.128

// smem layout (bytes)
constexpr int OFF_SE   = 0;                       // 384*132*4 = 202752
constexpr int OFF_SQV  = 202752;                  // 384*4     = 1536
constexpr int OFF_PD   = 204288;                  // 4*384*4   = 6144
constexpr int OFF_SLAB = 210432;                  // 384*4     = 1536
constexpr int OFF_WCNT = 211968;                  // 4*12*4    = 192
constexpr int OFF_WRED = 212160;                  // 24*4      = 96
constexpr int OFF_FLAG = 212256;                  // 16
constexpr int SMEM_BYTES = 212272;

__device__ float    g_psum[NB];
__device__ float    g_pcnt[NB];
__device__ unsigned g_ctr = 0;   // self-resetting ticket counter (wraps at NB-1)

__device__ __forceinline__ unsigned long long fma2(unsigned long long a,
                                                   unsigned long long b,
                                                   unsigned long long c) {
    unsigned long long d;
    asm("fma.rn.f32x2 %0, %1, %2, %3;" : "=l"(d) : "l"(a), "l"(b), "l"(c));
    return d;
}
__device__ __forceinline__ float lo32(unsigned long long v) {
    return __uint_as_float((unsigned)v);
}
__device__ __forceinline__ float hi32(unsigned long long v) {
    return __uint_as_float((unsigned)(v >> 32));
}

__global__ void __launch_bounds__(NPTS, 1)
fused_triplet_kernel(const float* __restrict__ E,
                     const int* __restrict__ labels,
                     float* __restrict__ out)
{
    extern __shared__ char sm[];
    float* sE    = (float*)(sm + OFF_SE);
    float* sqv   = (float*)(sm + OFF_SQV);
    float* pdist = (float*)(sm + OFF_PD);
    int*   slab  = (int*)  (sm + OFF_SLAB);
    int*   wcnt  = (int*)  (sm + OFF_WCNT);
    float* wred  = (float*)(sm + OFF_WRED);
    int*   sflag = (int*)  (sm + OFF_FLAG);

    const int t    = threadIdx.x;
    const int lane = t & 31;
    const int w    = t >> 5;
    const int b    = blockIdx.x;
    const int a0   = b * APB;

    // ---- stage labels + E into smem (coalesced float4 loads) ----
    slab[t] = labels[t];
    const float4* E4 = (const float4*)E;
    #pragma unroll
    for (int it = 0; it < 32; it++) {
        int idx = t + it * NPTS;            // 0..12287 = 384*32
        int r = idx >> 5, c = idx & 31;     // row, float4-col
        *(float4*)&sE[r * ROWF + c * 4] = E4[idx];
    }
    __syncthreads();

    // ---- dot(e_t, e_anchor) for 4 anchors + own squared norm, packed f32x2 ----
    unsigned long long acc0 = 0, acc1 = 0, acc2 = 0, acc3 = 0, accq = 0;
    const ulonglong2* my = (const ulonglong2*)&sE[t * ROWF];
    const ulonglong2* A0 = (const ulonglong2*)&sE[(a0 + 0) * ROWF];
    const ulonglong2* A1 = (const ulonglong2*)&sE[(a0 + 1) * ROWF];
    const ulonglong2* A2 = (const ulonglong2*)&sE[(a0 + 2) * ROWF];
    const ulonglong2* A3 = (const ulonglong2*)&sE[(a0 + 3) * ROWF];
    #pragma unroll
    for (int k = 0; k < DIM / 4; k++) {     // 32 iters, 16B (2 packed pairs) each
        ulonglong2 e  = my[k];
        ulonglong2 p0 = A0[k], p1 = A1[k], p2 = A2[k], p3 = A3[k];
        acc0 = fma2(e.x, p0.x, acc0); acc0 = fma2(e.y, p0.y, acc0);
        acc1 = fma2(e.x, p1.x, acc1); acc1 = fma2(e.y, p1.y, acc1);
        acc2 = fma2(e.x, p2.x, acc2); acc2 = fma2(e.y, p2.y, acc2);
        acc3 = fma2(e.x, p3.x, acc3); acc3 = fma2(e.y, p3.y, acc3);
        accq = fma2(e.x, e.x,  accq); accq = fma2(e.y, e.y,  accq);
    }
    float sq = lo32(accq) + hi32(accq);
    sqv[t] = sq;
    __syncthreads();

    // dist[i=anchor][j=t] = sq_i + sq_j - 2*dot  (reference op ordering)
    float dist[APB];
    dist[0] = (sqv[a0 + 0] + sq) - 2.0f * (lo32(acc0) + hi32(acc0));
    dist[1] = (sqv[a0 + 1] + sq) - 2.0f * (lo32(acc1) + hi32(acc1));
    dist[2] = (sqv[a0 + 2] + sq) - 2.0f * (lo32(acc2) + hi32(acc2));
    dist[3] = (sqv[a0 + 3] + sq) - 2.0f * (lo32(acc3) + hi32(acc3));

    // ---- deterministic positive compaction (ballot ranks), all 4 anchors ----
    const int myl = slab[t];
    bool     isp[APB];
    unsigned msk[APB];
    #pragma unroll
    for (int u = 0; u < APB; u++) {
        isp[u] = (myl == slab[a0 + u]);     // includes t == anchor (diagonal kept)
        msk[u] = __ballot_sync(0xffffffffu, isp[u]);
        if (lane == 0) wcnt[u * 12 + w] = __popc(msk[u]);
    }
    __syncthreads();

    int P[APB];
    #pragma unroll
    for (int u = 0; u < APB; u++) {
        int base = 0, tot = 0;
        #pragma unroll
        for (int w2 = 0; w2 < 12; w2++) {
            int cc = wcnt[u * 12 + w2];
            tot += cc;
            if (w2 < w) base += cc;
        }
        P[u] = tot;
        if (isp[u]) {
            int rank = base + __popc(msk[u] & ((1u << lane) - 1u));
            pdist[u * NPTS + rank] = dist[u];
        }
    }
    __syncthreads();

    // ---- triplet accumulation: thread t = negative n, loop compacted positives ----
    float s = 0.0f, c = 0.0f;
    #pragma unroll
    for (int u = 0; u < APB; u++) {
        if (!isp[u]) {
            const float c0 = MARGIN_F - dist[u];   // L = d_p + (m - d_n)
            const float* pd = &pdist[u * NPTS];
            const int Pu = P[u];
            #pragma unroll 4
            for (int p = 0; p < Pu; p++) {
                float L = pd[p] + c0;
                if (L > 0.0f && L < MARGIN_F) { s += L; c += 1.0f; }
            }
        }
    }

    // ---- block reduction ----
    #pragma unroll
    for (int o = 16; o > 0; o >>= 1) {
        s += __shfl_down_sync(0xffffffffu, s, o);
        c += __shfl_down_sync(0xffffffffu, c, o);
    }
    if (lane == 0) { wred[w] = s; wred[12 + w] = c; }
    __syncthreads();

    if (t == 0) {
        float S = 0.0f, C = 0.0f;
        #pragma unroll
        for (int w2 = 0; w2 < 12; w2++) { S += wred[w2]; C += wred[12 + w2]; }
        g_psum[b] = S;
        g_pcnt[b] = C;
        __threadfence();
        unsigned tk = atomicInc(&g_ctr, NB - 1u);   // wraps to 0 after full grid
        sflag[0] = (tk == NB - 1u) ? 1 : 0;
    }
    __syncthreads();

    // ---- last block finalizes: reduce 96 partials, write out ----
    if (sflag[0]) {
        float s2 = 0.0f, c2 = 0.0f;
        if (t < NB) {
            s2 = __ldcg(&g_psum[t]);
            c2 = __ldcg(&g_pcnt[t]);
        }
        #pragma unroll
        for (int o = 16; o > 0; o >>= 1) {
            s2 += __shfl_down_sync(0xffffffffu, s2, o);
            c2 += __shfl_down_sync(0xffffffffu, c2, o);
        }
        if (lane == 0) { wred[w] = s2; wred[12 + w] = c2; }
        __syncthreads();
        if (t == 0) {
            float S = 0.0f, C = 0.0f;
            #pragma unroll
            for (int w2 = 0; w2 < 12; w2++) { S += wred[w2]; C += wred[12 + w2]; }
            out[0] = S;
            out[1] = C;
        }
    }
}

extern "C" void kernel_launch(void* const* d_in, const int* in_sizes, int n_in,
                              void* d_out, int out_size) {
    const float* E      = (const float*)d_in[0];   // embeddings [384,128] f32
    const int*   labels = (const int*)d_in[1];     // labels [384] i32
    float* out = (float*)d_out;                    // [losses, count] f32

    cudaFuncSetAttribute(fused_triplet_kernel,
                         cudaFuncAttributeMaxDynamicSharedMemorySize, SMEM_BYTES);
    fused_triplet_kernel<<<NB, NPTS, SMEM_BYTES>>>(E, labels, out);
}